// round 1
// baseline (speedup 1.0000x reference)
#include <cuda_runtime.h>
#include <cstdint>

// Problem constants
#define B_ 2
#define H_ 8
#define N_ 512
#define D_ 16
#define E_ 128
#define HD 128              // H_*D_
#define COLS 256            // 2*HD : [Wz1 cols | Wz2 cols]
#define TM 32               // m-tile
#define NTILES (N_ / TM)    // 16
#define THREADS 256

// Shared memory layout (bytes)
#define SM_W     0
#define SM_W_SZ  (64 * COLS * 8)          // 131072 : packed f32x2 W, [e2][col]
#define SM_Z     (SM_W + SM_W_SZ)
#define SM_Z_SZ  (2 * TM * E_ * 4)        // 32768  : double-buffered z tile
#define SM_P     (SM_Z + SM_Z_SZ)
#define SM_P_SZ  (TM * COLS * 4)          // 32768  : projection tile
#define SM_S     (SM_P + SM_P_SZ)
#define SM_S_SZ  (H_ * N_ * 4)            // 16384  : scores [h][m]
#define SM_Q     (SM_S + SM_S_SZ)         // 512    : q row, head-major
#define SM_TOTAL (SM_Q + HD * 4)          // 213504 B total

__device__ __forceinline__ uint32_t smem_u32(const void* p) {
    uint32_t r;
    asm("{ .reg .u64 t; cvta.to.shared.u64 t, %1; cvt.u32.u64 %0, t; }"
        : "=r"(r) : "l"(p));
    return r;
}
__device__ __forceinline__ void cp16(uint32_t s, const void* g) {
    asm volatile("cp.async.cg.shared.global [%0], [%1], 16;" :: "r"(s), "l"(g));
}
#define CP_COMMIT() asm volatile("cp.async.commit_group;" ::: "memory")
#define CP_WAIT(n)  asm volatile("cp.async.wait_group %0;" :: "n"(n) : "memory")
// Packed dual-FMA: acc.{lo,hi} += a.{lo,hi} * b.{lo,hi}  (Blackwell f32x2 pipe)
#define FMA2(acc, a, b) asm("fma.rn.f32x2 %0, %1, %2, %0;" : "+l"(acc) : "l"(a), "l"(b))

__global__ void __launch_bounds__(THREADS, 1)
mixed_attn_kernel(const float* __restrict__ q, const float* __restrict__ k,
                  const float* __restrict__ v, const float* __restrict__ z,
                  const float* __restrict__ Wz1, const float* __restrict__ Wz2,
                  float* __restrict__ out)
{
    extern __shared__ char smem[];
    uint64_t* W_sm = (uint64_t*)(smem + SM_W);   // [64][COLS] packed (W[2e2],W[2e2+1])
    float*    z_sm = (float*)(smem + SM_Z);      // [2][TM][E]
    float*    p_sm = (float*)(smem + SM_P);      // [TM][COLS]
    float*    s_sm = (float*)(smem + SM_S);      // [H][N]
    float*    q_sm = (float*)(smem + SM_Q);      // [HD]

    const int tid = threadIdx.x;
    const int n   = blockIdx.x;
    const int b   = blockIdx.y;

    // ---- Load W into smem, pre-packed as f32x2 along E: W_sm[e2][col] = {W[2e2][c], W[2e2+1][c]}
    {
        const int col = tid;
        const float* Wsrc = (col < HD) ? Wz1 : Wz2;
        const int c = col & (HD - 1);
        #pragma unroll 4
        for (int e2 = 0; e2 < 64; e2++) {
            float lo = Wsrc[(2 * e2) * HD + c];
            float hi = Wsrc[(2 * e2 + 1) * HD + c];
            W_sm[e2 * COLS + col] =
                ((uint64_t)__float_as_uint(hi) << 32) | (uint64_t)__float_as_uint(lo);
        }
    }
    // ---- Load q[b, :, n, :] head-major
    if (tid < HD) {
        int h = tid >> 4, d = tid & 15;
        q_sm[tid] = q[(((size_t)b * H_ + h) * N_ + n) * D_ + d];
    }

    const float* ztile_base = z + (((size_t)b * N_ + n) * N_) * E_;
    const uint32_t z_sm_u = smem_u32(z_sm);

    // Prefetch tile 0 (contiguous 16 KB block, fully coalesced)
    {
        const char* g = (const char*)ztile_base;
        #pragma unroll
        for (int i = 0; i < 4; i++)
            cp16(z_sm_u + (tid + i * THREADS) * 16, g + (tid + i * THREADS) * 16);
        CP_COMMIT();
    }

    for (int t = 0; t < NTILES; t++) {
        if (t + 1 < NTILES) {
            const char* g = (const char*)(ztile_base + (size_t)(t + 1) * TM * E_);
            uint32_t s = z_sm_u + ((t + 1) & 1) * (TM * E_ * 4);
            #pragma unroll
            for (int i = 0; i < 4; i++)
                cp16(s + (tid + i * THREADS) * 16, g + (tid + i * THREADS) * 16);
            CP_COMMIT();
            CP_WAIT(1);
        } else {
            CP_WAIT(0);
        }
        __syncthreads();  // z tile t ready; previous score phase done with p_sm

        // ---- Projection: each thread owns output column `tid`, 32 m-rows.
        // acc holds (sum over even e, sum over odd e) packed.
        uint64_t pacc[TM];
        #pragma unroll
        for (int m = 0; m < TM; m++) pacc[m] = 0ull;

        const uint64_t* Wp = W_sm + tid;
        const uint64_t* zp = (const uint64_t*)(z_sm + (t & 1) * (TM * E_));
        #pragma unroll 1
        for (int e2 = 0; e2 < 64; e2 += 2) {
            uint64_t w0 = Wp[e2 * COLS];
            uint64_t w1 = Wp[(e2 + 1) * COLS];
            #pragma unroll
            for (int m = 0; m < TM; m++) {
                uint64_t z0 = zp[m * 64 + e2];      // {z[m][2e2],   z[m][2e2+1]} broadcast
                uint64_t z1 = zp[m * 64 + e2 + 1];
                FMA2(pacc[m], z0, w0);
                FMA2(pacc[m], z1, w1);
            }
        }
        #pragma unroll
        for (int m = 0; m < TM; m++) {
            float lo = __uint_as_float((uint32_t)pacc[m]);
            float hi = __uint_as_float((uint32_t)(pacc[m] >> 32));
            p_sm[m * COLS + tid] = lo + hi;
        }
        __syncthreads();  // p tile visible to score phase

        // ---- Scores: one thread per (m_local, h). score = (q+z1)·(k+z2) / 4
        {
            const int m_l = tid >> 3;
            const int h   = tid & 7;
            const int m_g = t * TM + m_l;
            const float4* kp = (const float4*)(k + (((size_t)b * H_ + h) * N_ + m_g) * D_);
            const float4* p1 = (const float4*)(p_sm + m_l * COLS + h * D_);
            const float4* p2 = (const float4*)(p_sm + m_l * COLS + HD + h * D_);
            const float4* qh = (const float4*)(q_sm + h * D_);
            float s = 0.f;
            #pragma unroll
            for (int i = 0; i < 4; i++) {
                float4 kv = kp[i], a = p1[i], c = p2[i], qv = qh[i];
                s += (qv.x + a.x) * (kv.x + c.x);
                s += (qv.y + a.y) * (kv.y + c.y);
                s += (qv.z + a.z) * (kv.z + c.z);
                s += (qv.w + a.w) * (kv.w + c.w);
            }
            s_sm[h * N_ + m_g] = s * 0.25f;  // 1/sqrt(D), D=16
        }
    }
    __syncthreads();

    // ---- Softmax + output: warp w handles head w.
    {
        const int w    = tid >> 5;
        const int lane = tid & 31;
        float* srow = s_sm + w * N_;

        float mx = -1e30f;
        for (int m = lane; m < N_; m += 32) mx = fmaxf(mx, srow[m]);
        #pragma unroll
        for (int o = 16; o > 0; o >>= 1) mx = fmaxf(mx, __shfl_xor_sync(0xffffffffu, mx, o));

        float sum = 0.f;
        for (int m = lane; m < N_; m += 32) {
            float e = __expf(srow[m] - mx);
            srow[m] = e;
            sum += e;
        }
        #pragma unroll
        for (int o = 16; o > 0; o >>= 1) sum += __shfl_xor_sync(0xffffffffu, sum, o);
        __syncwarp();  // exp values written by all lanes visible

        // lane = d + 16*half ; each half accumulates 256 m's, then one xor-16 combine
        const int d    = lane & 15;
        const int half = lane >> 4;
        const float* vp = v + (((size_t)b * H_ + w) * N_) * D_;
        float oacc = 0.f;
        const int m0 = half * (N_ / 2);
        #pragma unroll 4
        for (int m = m0; m < m0 + N_ / 2; m++)
            oacc += srow[m] * vp[(size_t)m * D_ + d];
        oacc += __shfl_xor_sync(0xffffffffu, oacc, 16);
        if (half == 0)
            out[((size_t)b * N_ + n) * HD + w * D_ + d] = oacc / sum;
    }
}

extern "C" void kernel_launch(void* const* d_in, const int* in_sizes, int n_in,
                              void* d_out, int out_size) {
    const float* q   = (const float*)d_in[0];
    const float* k   = (const float*)d_in[1];
    const float* v   = (const float*)d_in[2];
    const float* z   = (const float*)d_in[3];
    const float* Wz1 = (const float*)d_in[4];
    const float* Wz2 = (const float*)d_in[5];
    float* out = (float*)d_out;

    cudaFuncSetAttribute(mixed_attn_kernel,
                         cudaFuncAttributeMaxDynamicSharedMemorySize, SM_TOTAL);
    dim3 grid(N_, B_);
    mixed_attn_kernel<<<grid, THREADS, SM_TOTAL>>>(q, k, v, z, Wz1, Wz2, out);
}

// round 2
// speedup vs baseline: 1.2259x; 1.2259x over previous
#include <cuda_runtime.h>
#include <cstdint>

// Problem constants
#define B_ 2
#define H_ 8
#define N_ 512
#define D_ 16
#define E_ 128
#define HD 128              // H_*D_
#define COLS 256            // 2*HD : [Wz1 cols | Wz2 cols]
#define TM 32               // m-tile
#define NTILES (N_ / TM)    // 16
#define THREADS 256

// Shared memory layout (bytes)
#define SM_W     0
#define SM_W_SZ  (64 * COLS * 8)          // 131072 : packed f32x2 W, [e2][col]
#define SM_Z     (SM_W + SM_W_SZ)
#define SM_Z_SZ  (2 * TM * E_ * 4)        // 32768  : double-buffered z tile
#define SM_P     (SM_Z + SM_Z_SZ)
#define SM_P_SZ  (TM * COLS * 4)          // 32768  : projection tile
#define SM_S     (SM_P + SM_P_SZ)
#define SM_S_SZ  (H_ * N_ * 4)            // 16384  : scores [h][m]
#define SM_Q     (SM_S + SM_S_SZ)         // 512    : q row, head-major
#define SM_TOTAL (SM_Q + HD * 4)          // 213504 B total

__device__ __forceinline__ uint32_t smem_u32(const void* p) {
    uint32_t r;
    asm("{ .reg .u64 t; cvta.to.shared.u64 t, %1; cvt.u32.u64 %0, t; }"
        : "=r"(r) : "l"(p));
    return r;
}
__device__ __forceinline__ void cp16(uint32_t s, const void* g) {
    asm volatile("cp.async.cg.shared.global [%0], [%1], 16;" :: "r"(s), "l"(g));
}
#define CP_COMMIT() asm volatile("cp.async.commit_group;" ::: "memory")
#define CP_WAIT(n)  asm volatile("cp.async.wait_group %0;" :: "n"(n) : "memory")
// Packed dual-FMA: acc.{lo,hi} += a.{lo,hi} * b.{lo,hi}  (Blackwell f32x2 pipe)
#define FMA2(acc, a, b) asm("fma.rn.f32x2 %0, %1, %2, %0;" : "+l"(acc) : "l"(a), "l"(b))

__global__ void __launch_bounds__(THREADS, 1)
mixed_attn_kernel(const float* __restrict__ q, const float* __restrict__ k,
                  const float* __restrict__ v, const float* __restrict__ z,
                  const float* __restrict__ Wz1, const float* __restrict__ Wz2,
                  float* __restrict__ out)
{
    extern __shared__ char smem[];
    uint64_t* W_sm = (uint64_t*)(smem + SM_W);   // [64][COLS] packed (W[2e2],W[2e2+1])
    float*    z_sm = (float*)(smem + SM_Z);      // [2][TM][E]
    float*    p_sm = (float*)(smem + SM_P);      // [TM][COLS]
    float*    s_sm = (float*)(smem + SM_S);      // [H][N]
    float*    q_sm = (float*)(smem + SM_Q);      // [HD]

    const int tid = threadIdx.x;
    const int n   = blockIdx.x;
    const int b   = blockIdx.y;

    // Projection register-tile mapping:
    //   colg = tid & 63  -> owns columns {colg, colg+64, colg+128, colg+192}
    //   mg   = tid >> 6  -> owns m rows  {8*mg .. 8*mg+7}
    const int colg = tid & 63;
    const int mg   = tid >> 6;

    // ---- Load W into smem, pre-packed as f32x2 along E: W_sm[e2][col] = {W[2e2][c], W[2e2+1][c]}
    {
        const int col = tid;
        const float* Wsrc = (col < HD) ? Wz1 : Wz2;
        const int c = col & (HD - 1);
        #pragma unroll 4
        for (int e2 = 0; e2 < 64; e2++) {
            float lo = Wsrc[(2 * e2) * HD + c];
            float hi = Wsrc[(2 * e2 + 1) * HD + c];
            W_sm[e2 * COLS + col] =
                ((uint64_t)__float_as_uint(hi) << 32) | (uint64_t)__float_as_uint(lo);
        }
    }
    // ---- Load q[b, :, n, :] head-major
    if (tid < HD) {
        int h = tid >> 4, d = tid & 15;
        q_sm[tid] = q[(((size_t)b * H_ + h) * N_ + n) * D_ + d];
    }

    const float* ztile_base = z + (((size_t)b * N_ + n) * N_) * E_;
    const uint32_t z_sm_u = smem_u32(z_sm);

    // Prefetch tile 0 (contiguous 16 KB block, fully coalesced)
    {
        const char* g = (const char*)ztile_base;
        #pragma unroll
        for (int i = 0; i < 4; i++)
            cp16(z_sm_u + (tid + i * THREADS) * 16, g + (tid + i * THREADS) * 16);
        CP_COMMIT();
    }

    for (int t = 0; t < NTILES; t++) {
        if (t + 1 < NTILES) {
            const char* g = (const char*)(ztile_base + (size_t)(t + 1) * TM * E_);
            uint32_t s = z_sm_u + ((t + 1) & 1) * (TM * E_ * 4);
            #pragma unroll
            for (int i = 0; i < 4; i++)
                cp16(s + (tid + i * THREADS) * 16, g + (tid + i * THREADS) * 16);
            CP_COMMIT();
            CP_WAIT(1);
        } else {
            CP_WAIT(0);
        }
        __syncthreads();  // z tile t ready; previous score phase done with p_sm

        // ---- Projection: 4 cols x 8 m register tile per thread.
        // acc[m][j] packs (sum over even e, sum over odd e).
        uint64_t acc[8][4];
        #pragma unroll
        for (int m = 0; m < 8; m++)
            #pragma unroll
            for (int j = 0; j < 4; j++) acc[m][j] = 0ull;

        const uint64_t* zb =
            (const uint64_t*)(z_sm + (t & 1) * (TM * E_)) + mg * 8 * 64;
        const uint64_t* Wb = W_sm + colg;

        #pragma unroll 2
        for (int e2 = 0; e2 < 64; e2 += 2) {
            uint64_t w0[4], w1[4];
            #pragma unroll
            for (int j = 0; j < 4; j++) {
                w0[j] = Wb[e2 * COLS + j * 64];        // coalesced LDS.64
                w1[j] = Wb[(e2 + 1) * COLS + j * 64];
            }
            #pragma unroll
            for (int m = 0; m < 8; m++) {
                ulonglong2 zz = *(const ulonglong2*)(zb + m * 64 + e2);  // broadcast LDS.128
                #pragma unroll
                for (int j = 0; j < 4; j++) {
                    FMA2(acc[m][j], zz.x, w0[j]);
                    FMA2(acc[m][j], zz.y, w1[j]);
                }
            }
        }
        #pragma unroll
        for (int m = 0; m < 8; m++) {
            #pragma unroll
            for (int j = 0; j < 4; j++) {
                float lo = __uint_as_float((uint32_t)acc[m][j]);
                float hi = __uint_as_float((uint32_t)(acc[m][j] >> 32));
                p_sm[(mg * 8 + m) * COLS + j * 64 + colg] = lo + hi;
            }
        }
        __syncthreads();  // p tile visible to score phase

        // ---- Scores: one thread per (m_local, h). score = (q+z1)·(k+z2) / 4
        {
            const int m_l = tid >> 3;
            const int h   = tid & 7;
            const int m_g = t * TM + m_l;
            const float4* kp = (const float4*)(k + (((size_t)b * H_ + h) * N_ + m_g) * D_);
            const float4* p1 = (const float4*)(p_sm + m_l * COLS + h * D_);
            const float4* p2 = (const float4*)(p_sm + m_l * COLS + HD + h * D_);
            const float4* qh = (const float4*)(q_sm + h * D_);
            float s = 0.f;
            #pragma unroll
            for (int i = 0; i < 4; i++) {
                float4 kv = kp[i], a = p1[i], c = p2[i], qv = qh[i];
                s += (qv.x + a.x) * (kv.x + c.x);
                s += (qv.y + a.y) * (kv.y + c.y);
                s += (qv.z + a.z) * (kv.z + c.z);
                s += (qv.w + a.w) * (kv.w + c.w);
            }
            s_sm[h * N_ + m_g] = s * 0.25f;  // 1/sqrt(D), D=16
        }
    }
    __syncthreads();

    // ---- Softmax + output: warp w handles head w.
    {
        const int w    = tid >> 5;
        const int lane = tid & 31;
        float* srow = s_sm + w * N_;

        float mx = -1e30f;
        for (int m = lane; m < N_; m += 32) mx = fmaxf(mx, srow[m]);
        #pragma unroll
        for (int o = 16; o > 0; o >>= 1) mx = fmaxf(mx, __shfl_xor_sync(0xffffffffu, mx, o));

        float sum = 0.f;
        for (int m = lane; m < N_; m += 32) {
            float e = __expf(srow[m] - mx);
            srow[m] = e;
            sum += e;
        }
        #pragma unroll
        for (int o = 16; o > 0; o >>= 1) sum += __shfl_xor_sync(0xffffffffu, sum, o);
        __syncwarp();  // exp values written by all lanes visible

        // lane = d + 16*half ; each half accumulates 256 m's, then one xor-16 combine
        const int d    = lane & 15;
        const int half = lane >> 4;
        const float* vp = v + (((size_t)b * H_ + w) * N_) * D_;
        float oacc = 0.f;
        const int m0 = half * (N_ / 2);
        #pragma unroll 4
        for (int m = m0; m < m0 + N_ / 2; m++)
            oacc += srow[m] * vp[(size_t)m * D_ + d];
        oacc += __shfl_xor_sync(0xffffffffu, oacc, 16);
        if (half == 0)
            out[((size_t)b * N_ + n) * HD + w * D_ + d] = oacc / sum;
    }
}

extern "C" void kernel_launch(void* const* d_in, const int* in_sizes, int n_in,
                              void* d_out, int out_size) {
    const float* q   = (const float*)d_in[0];
    const float* k   = (const float*)d_in[1];
    const float* v   = (const float*)d_in[2];
    const float* z   = (const float*)d_in[3];
    const float* Wz1 = (const float*)d_in[4];
    const float* Wz2 = (const float*)d_in[5];
    float* out = (float*)d_out;

    cudaFuncSetAttribute(mixed_attn_kernel,
                         cudaFuncAttributeMaxDynamicSharedMemorySize, SM_TOTAL);
    dim3 grid(N_, B_);
    mixed_attn_kernel<<<grid, THREADS, SM_TOTAL>>>(q, k, v, z, Wz1, Wz2, out);
}

// round 4
// speedup vs baseline: 2.6186x; 2.1361x over previous
#include <cuda_runtime.h>
#include <cuda_bf16.h>
#include <cstdint>

// Problem constants
#define B_ 2
#define H_ 8
#define N_ 512
#define D_ 16
#define E_ 128
#define HD 128
#define TM 128              // m-rows per tile
#define NTILES 4
#define THREADS 256

// smem layout (bytes). Rows of A/W are 128 bf16 = 256 B.
#define SM_Q     0                      // 512 B   q row, head-major
#define SM_S     512                    // 16384 B scores [H][N]
#define SM_AH    17408                  // 32768 B z_hi  [128m][128k] bf16
#define SM_AL    (SM_AH + 32768)        // 32768 B z_lo
#define SM_WH    (SM_AL + 32768)        // 65536 B W_hi  [256n][128k] bf16 (cols interleaved Wz1/Wz2)
#define SM_WL    (SM_WH + 65536)        // 65536 B W_lo
#define SM_TOTAL (SM_WL + 65536)        // 214016 B

__device__ __forceinline__ uint32_t smem_u32(const void* p) {
    uint32_t r;
    asm("{ .reg .u64 t; cvta.to.shared.u64 t, %1; cvt.u32.u64 %0, t; }" : "=r"(r) : "l"(p));
    return r;
}
__device__ __forceinline__ void ldsm_x4(uint32_t (&r)[4], uint32_t addr) {
    asm volatile("ldmatrix.sync.aligned.m8n8.x4.shared.b16 {%0,%1,%2,%3}, [%4];"
                 : "=r"(r[0]), "=r"(r[1]), "=r"(r[2]), "=r"(r[3]) : "r"(addr));
}
#define MMA_BF16(d, a, b0v, b1v) \
    asm volatile("mma.sync.aligned.m16n8k16.row.col.f32.bf16.bf16.f32 " \
        "{%0,%1,%2,%3}, {%4,%5,%6,%7}, {%8,%9}, {%0,%1,%2,%3};" \
        : "+f"((d)[0]), "+f"((d)[1]), "+f"((d)[2]), "+f"((d)[3]) \
        : "r"((a)[0]), "r"((a)[1]), "r"((a)[2]), "r"((a)[3]), "r"(b0v), "r"(b1v))

// split a float pair into bf16 hi word (+ residuals)
__device__ __forceinline__ uint32_t pack_bf2(float a, float b) {
    __nv_bfloat162 p = __float22bfloat162_rn(make_float2(a, b));  // .x=a (low half)
    return *reinterpret_cast<uint32_t*>(&p);
}
__device__ __forceinline__ float bf_lo(uint32_t w) { return __uint_as_float(w << 16); }
__device__ __forceinline__ float bf_hi(uint32_t w) { return __uint_as_float(w & 0xFFFF0000u); }

__global__ void __launch_bounds__(THREADS, 1)
mixed_attn_hmma(const float* __restrict__ q, const float* __restrict__ k,
                const float* __restrict__ v, const float* __restrict__ z,
                const float* __restrict__ Wz1, const float* __restrict__ Wz2,
                float* __restrict__ out)
{
    extern __shared__ char smem[];
    const uint32_t smem_base = smem_u32(smem);
    float* q_sm = (float*)(smem + SM_Q);
    float* s_sm = (float*)(smem + SM_S);

    const int tid  = threadIdx.x;
    const int wid  = tid >> 5;
    const int lane = tid & 31;
    const int g    = lane >> 2;
    const int tig  = lane & 3;
    const int n = blockIdx.x, b = blockIdx.y;

    // ---- q row, head-major
    if (tid < HD) {
        int h = tid >> 4, d = tid & 15;
        q_sm[tid] = q[(((size_t)b * H_ + h) * N_ + n) * D_ + d];
    }

    // ---- W -> bf16 hi/lo, column-interleaved: smem row nn: even->Wz1[:,nn/2], odd->Wz2[:,nn/2]
    {
        const int nn = tid;
        const float* Wsrc = (nn & 1) ? Wz2 : Wz1;
        const int c = nn >> 1;
        char* WH = smem + SM_WH + nn * 256;
        char* WL = smem + SM_WL + nn * 256;
        const int xr = (nn & 7);
        #pragma unroll 4
        for (int e = 0; e < E_; e += 2) {
            float w0 = Wsrc[e * HD + c];
            float w1 = Wsrc[(e + 1) * HD + c];
            uint32_t hi = pack_bf2(w0, w1);
            uint32_t lo = pack_bf2(w0 - bf_lo(hi), w1 - bf_hi(hi));
            int sw = ((((e >> 3) ^ xr) << 4)) + (e & 7) * 2;
            *(uint32_t*)(WH + sw) = hi;
            *(uint32_t*)(WL + sw) = lo;
        }
    }

    // ---- z tile 0 prefetch: thread owns row mrow, e half e0
    const int mrow = tid >> 1;
    const int e0   = (tid & 1) * 64;
    const float* zrow = z + (((size_t)b * N_ + n) * N_ + mrow) * E_ + e0;
    float4 zreg[16];
    #pragma unroll
    for (int j = 0; j < 16; j++) zreg[j] = ((const float4*)zrow)[j];

    __syncthreads();   // W, q ready

    // warp tiling: m-block 32 rows, n-block 128 cols (=4 heads)
    const int mblk  = (wid & 3) * 32;
    const int nbase = (wid >> 2) * 128;

    // lane-invariant ldmatrix address pieces (row&7 == lane&7 for all our tiles)
    const int laneX = lane & 7;
    const uint32_t arow = smem_base + (uint32_t)(mblk + ((lane >> 3) & 1) * 8 + laneX) * 256;
    const int asel = lane >> 4;          // k-half select for A
    const uint32_t brow = smem_base + (uint32_t)(nbase + ((lane >> 4) & 1) * 8 + laneX) * 256;
    const int bsel = (lane >> 3) & 1;    // k-half select for B

    for (int t = 0; t < NTILES; t++) {
        // ---- convert zreg -> A_sm hi/lo (swizzled)
        {
            char* AH = smem + SM_AH + mrow * 256;
            char* AL = smem + SM_AL + mrow * 256;
            const int xr = mrow & 7;
            #pragma unroll
            for (int j = 0; j < 16; j++) {
                const int e = e0 + j * 4;
                float4 f = zreg[j];
                uint32_t h01 = pack_bf2(f.x, f.y);
                uint32_t h23 = pack_bf2(f.z, f.w);
                uint32_t l01 = pack_bf2(f.x - bf_lo(h01), f.y - bf_hi(h01));
                uint32_t l23 = pack_bf2(f.z - bf_lo(h23), f.w - bf_hi(h23));
                int sw = (((e >> 3) ^ xr) << 4) + (e & 4) * 2;
                *(uint2*)(AH + sw) = make_uint2(h01, h23);
                *(uint2*)(AL + sw) = make_uint2(l01, l23);
            }
        }
        __syncthreads();   // A tile visible to all warps

        // prefetch next z tile (long-latency, overlaps MMA phase)
        if (t + 1 < NTILES) {
            const float4* zp = (const float4*)(zrow + (size_t)(t + 1) * TM * E_);
            #pragma unroll
            for (int j = 0; j < 16; j++) zreg[j] = zp[j];
        }

        // ---- MMA + fused score epilogue, two n-halves of 64 cols (2 heads each)
        #pragma unroll 1
        for (int nh = 0; nh < 2; nh++) {
            float acc[2][8][4];
            #pragma unroll
            for (int mt = 0; mt < 2; mt++)
                #pragma unroll
                for (int nt = 0; nt < 8; nt++)
                    #pragma unroll
                    for (int i = 0; i < 4; i++) acc[mt][nt][i] = 0.f;

            const uint32_t bROW = brow + (uint32_t)nh * (64 * 256);

            #pragma unroll 1
            for (int ks = 0; ks < 8; ks++) {
                uint32_t ah[2][4], al[2][4];
                const uint32_t aoff = arow + ((uint32_t)((ks * 2 + asel) ^ laneX) << 4);
                ldsm_x4(ah[0], aoff + SM_AH);
                ldsm_x4(ah[1], aoff + SM_AH + 16 * 256);
                ldsm_x4(al[0], aoff + SM_AL);
                ldsm_x4(al[1], aoff + SM_AL + 16 * 256);
                const uint32_t boff = ((uint32_t)((ks * 2 + bsel) ^ laneX) << 4);
                #pragma unroll
                for (int ntp = 0; ntp < 4; ntp++) {
                    uint32_t bh[4], bl[4];
                    const uint32_t ba = bROW + (uint32_t)ntp * (16 * 256) + boff;
                    ldsm_x4(bh, ba + SM_WH);
                    ldsm_x4(bl, ba + SM_WL);
                    #pragma unroll
                    for (int mt = 0; mt < 2; mt++) {
                        MMA_BF16(acc[mt][2 * ntp],     ah[mt], bh[0], bh[1]);
                        MMA_BF16(acc[mt][2 * ntp + 1], ah[mt], bh[2], bh[3]);
                        MMA_BF16(acc[mt][2 * ntp],     ah[mt], bl[0], bl[1]);
                        MMA_BF16(acc[mt][2 * ntp + 1], ah[mt], bl[2], bl[3]);
                        MMA_BF16(acc[mt][2 * ntp],     al[mt], bh[0], bh[1]);
                        MMA_BF16(acc[mt][2 * ntp + 1], al[mt], bh[2], bh[3]);
                    }
                }
            }

            // ---- scores straight from fragments:
            // col pair (2j, 2j+1) = (p1[j], p2[j]), j = h*16+d
            const int h0 = (nbase + nh * 64) >> 5;   // first head of this n-half
            #pragma unroll
            for (int hh = 0; hh < 2; hh++) {
                const int h = h0 + hh;
                const float* kh = k + (((size_t)b * H_ + h) * N_) * D_;
                const float* qh = q_sm + h * 16;
                float sa[2][2] = {{0.f, 0.f}, {0.f, 0.f}};
                #pragma unroll
                for (int ntl = 0; ntl < 4; ntl++) {
                    const int nt = hh * 4 + ntl;
                    const int d = ntl * 4 + tig;
                    const float qv = qh[d];
                    #pragma unroll
                    for (int mt = 0; mt < 2; mt++) {
                        const int mg = t * TM + mblk + mt * 16 + g;
                        float kv0 = kh[(size_t)mg * 16 + d];
                        float kv1 = kh[(size_t)(mg + 8) * 16 + d];
                        sa[mt][0] += (qv + acc[mt][nt][0]) * (kv0 + acc[mt][nt][1]);
                        sa[mt][1] += (qv + acc[mt][nt][2]) * (kv1 + acc[mt][nt][3]);
                    }
                }
                #pragma unroll
                for (int mt = 0; mt < 2; mt++)
                    #pragma unroll
                    for (int r = 0; r < 2; r++) {
                        float s = sa[mt][r];
                        s += __shfl_xor_sync(0xffffffffu, s, 1);
                        s += __shfl_xor_sync(0xffffffffu, s, 2);
                        if (tig == 0) {
                            const int mg = t * TM + mblk + mt * 16 + g + r * 8;
                            s_sm[h * N_ + mg] = s * 0.25f;   // 1/sqrt(D), D=16
                        }
                    }
            }
        }
        __syncthreads();   // all warps done with A_sm before next tile overwrites
    }

    // ---- softmax + output: warp w handles head w
    {
        const int w = wid;
        float* srow = s_sm + w * N_;

        float mx = -1e30f;
        for (int m = lane; m < N_; m += 32) mx = fmaxf(mx, srow[m]);
        #pragma unroll
        for (int o = 16; o > 0; o >>= 1) mx = fmaxf(mx, __shfl_xor_sync(0xffffffffu, mx, o));

        float sum = 0.f;
        for (int m = lane; m < N_; m += 32) {
            float e = __expf(srow[m] - mx);
            srow[m] = e;
            sum += e;
        }
        #pragma unroll
        for (int o = 16; o > 0; o >>= 1) sum += __shfl_xor_sync(0xffffffffu, sum, o);
        __syncwarp();

        const int d    = lane & 15;
        const int half = lane >> 4;
        const float* vp = v + (((size_t)b * H_ + w) * N_) * D_;
        float oacc = 0.f;
        const int m0 = half * (N_ / 2);
        #pragma unroll 4
        for (int m = m0; m < m0 + N_ / 2; m++)
            oacc += srow[m] * vp[(size_t)m * D_ + d];
        oacc += __shfl_xor_sync(0xffffffffu, oacc, 16);
        if (half == 0)
            out[((size_t)b * N_ + n) * HD + w * D_ + d] = oacc / sum;
    }
}

extern "C" void kernel_launch(void* const* d_in, const int* in_sizes, int n_in,
                              void* d_out, int out_size) {
    const float* q   = (const float*)d_in[0];
    const float* k   = (const float*)d_in[1];
    const float* v   = (const float*)d_in[2];
    const float* z   = (const float*)d_in[3];
    const float* Wz1 = (const float*)d_in[4];
    const float* Wz2 = (const float*)d_in[5];
    float* out = (float*)d_out;

    cudaFuncSetAttribute(mixed_attn_hmma,
                         cudaFuncAttributeMaxDynamicSharedMemorySize, SM_TOTAL);
    dim3 grid(N_, B_);
    mixed_attn_hmma<<<grid, THREADS, SM_TOTAL>>>(q, k, v, z, Wz1, Wz2, out);
}

// round 5
// speedup vs baseline: 2.8698x; 1.0959x over previous
#include <cuda_runtime.h>
#include <cuda_bf16.h>
#include <cstdint>

// Problem constants
#define B_ 2
#define H_ 8
#define N_ 512
#define D_ 16
#define E_ 128
#define HD 128
#define TM 128              // m-rows per tile
#define NTILES 4
#define THREADS 512

// smem layout (bytes). Rows of A/W are 128 bf16 = 256 B.
#define SM_Q     0                      // 512 B   q row, head-major
#define SM_S     512                    // 16384 B scores [H][N]
#define SM_RED   16896                  // 64 B    softmax partial sums [H][2]
#define SM_OBUF  16960                  // 512 B   output half-partials [H][16]
#define SM_AH    17920                  // 32768 B z_hi  [128m][128k] bf16 (256B-aligned)
#define SM_AL    (SM_AH + 32768)        // 32768 B z_lo
#define SM_WH    (SM_AL + 32768)        // 65536 B W_hi  [256n][128k] bf16 (cols interleaved Wz1/Wz2)
#define SM_WL    (SM_WH + 65536)        // 65536 B W_lo
#define SM_TOTAL (SM_WL + 65536)        // 214528 B

__device__ __forceinline__ uint32_t smem_u32(const void* p) {
    uint32_t r;
    asm("{ .reg .u64 t; cvta.to.shared.u64 t, %1; cvt.u32.u64 %0, t; }" : "=r"(r) : "l"(p));
    return r;
}
__device__ __forceinline__ void ldsm_x4(uint32_t (&r)[4], uint32_t addr) {
    asm volatile("ldmatrix.sync.aligned.m8n8.x4.shared.b16 {%0,%1,%2,%3}, [%4];"
                 : "=r"(r[0]), "=r"(r[1]), "=r"(r[2]), "=r"(r[3]) : "r"(addr));
}
#define MMA_BF16(d, a, b0v, b1v) \
    asm volatile("mma.sync.aligned.m16n8k16.row.col.f32.bf16.bf16.f32 " \
        "{%0,%1,%2,%3}, {%4,%5,%6,%7}, {%8,%9}, {%0,%1,%2,%3};" \
        : "+f"((d)[0]), "+f"((d)[1]), "+f"((d)[2]), "+f"((d)[3]) \
        : "r"((a)[0]), "r"((a)[1]), "r"((a)[2]), "r"((a)[3]), "r"(b0v), "r"(b1v))

// split a float pair into bf16 hi word (+ residuals)
__device__ __forceinline__ uint32_t pack_bf2(float a, float b) {
    __nv_bfloat162 p = __float22bfloat162_rn(make_float2(a, b));  // .x=a (low half)
    return *reinterpret_cast<uint32_t*>(&p);
}
__device__ __forceinline__ float bf_lo(uint32_t w) { return __uint_as_float(w << 16); }
__device__ __forceinline__ float bf_hi(uint32_t w) { return __uint_as_float(w & 0xFFFF0000u); }

__global__ void __launch_bounds__(THREADS, 1)
mixed_attn_hmma(const float* __restrict__ q, const float* __restrict__ k,
                const float* __restrict__ v, const float* __restrict__ z,
                const float* __restrict__ Wz1, const float* __restrict__ Wz2,
                float* __restrict__ out)
{
    extern __shared__ char smem[];
    const uint32_t smem_base = smem_u32(smem);
    float* q_sm   = (float*)(smem + SM_Q);
    float* s_sm   = (float*)(smem + SM_S);
    float* red_sm = (float*)(smem + SM_RED);
    float* obuf   = (float*)(smem + SM_OBUF);

    const int tid  = threadIdx.x;
    const int wid  = tid >> 5;
    const int lane = tid & 31;
    const int g    = lane >> 2;
    const int tig  = lane & 3;
    const int n = blockIdx.x, b = blockIdx.y;

    // ---- q row, head-major
    if (tid < HD) {
        int h = tid >> 4, d = tid & 15;
        q_sm[tid] = q[(((size_t)b * H_ + h) * N_ + n) * D_ + d];
    }

    // ---- W -> bf16 hi/lo, column-interleaved: smem row nn: even->Wz1[:,nn/2], odd->Wz2[:,nn/2]
    // 2 threads per row, each 64 e-values.
    {
        const int nn = tid >> 1;
        const int eh = (tid & 1) * 64;
        const float* Wsrc = (nn & 1) ? Wz2 : Wz1;
        const int c = nn >> 1;
        char* WH = smem + SM_WH + nn * 256;
        char* WL = smem + SM_WL + nn * 256;
        const int xr = (nn & 7);
        #pragma unroll 4
        for (int e = eh; e < eh + 64; e += 2) {
            float w0 = Wsrc[e * HD + c];
            float w1 = Wsrc[(e + 1) * HD + c];
            uint32_t hi = pack_bf2(w0, w1);
            uint32_t lo = pack_bf2(w0 - bf_lo(hi), w1 - bf_hi(hi));
            int sw = ((((e >> 3) ^ xr) << 4)) + (e & 7) * 2;
            *(uint32_t*)(WH + sw) = hi;
            *(uint32_t*)(WL + sw) = lo;
        }
    }

    // ---- z tile 0 prefetch: thread owns row mrow, e-quarter e0 (32 floats = one 128B line)
    const int mrow = tid >> 2;
    const int e0   = (tid & 3) * 32;
    const float* zrow = z + (((size_t)b * N_ + n) * N_ + mrow) * E_ + e0;
    float4 zreg[8];
    #pragma unroll
    for (int j = 0; j < 8; j++) zreg[j] = ((const float4*)zrow)[j];

    __syncthreads();   // W, q ready

    // warp tiling: 16 warps = 4 m-blocks (32 rows) x 4 n-blocks (64 cols = 2 heads)
    const int mblk  = (wid & 3) * 32;
    const int nq    = wid >> 2;
    const int nbase = nq * 64;

    // lane-invariant ldmatrix address pieces (row&7 == lane&7 for all our tiles)
    const int laneX = lane & 7;
    const uint32_t arow = smem_base + (uint32_t)(mblk + ((lane >> 3) & 1) * 8 + laneX) * 256;
    const int asel = lane >> 4;          // k-half select for A
    const uint32_t brow = smem_base + (uint32_t)(nbase + ((lane >> 4) & 1) * 8 + laneX) * 256;
    const int bsel = (lane >> 3) & 1;    // k-half select for B

    for (int t = 0; t < NTILES; t++) {
        // ---- convert zreg -> A_sm hi/lo (swizzled)
        {
            char* AH = smem + SM_AH + mrow * 256;
            char* AL = smem + SM_AL + mrow * 256;
            const int xr = mrow & 7;
            #pragma unroll
            for (int j = 0; j < 8; j++) {
                const int e = e0 + j * 4;
                float4 f = zreg[j];
                uint32_t h01 = pack_bf2(f.x, f.y);
                uint32_t h23 = pack_bf2(f.z, f.w);
                uint32_t l01 = pack_bf2(f.x - bf_lo(h01), f.y - bf_hi(h01));
                uint32_t l23 = pack_bf2(f.z - bf_lo(h23), f.w - bf_hi(h23));
                int sw = (((e >> 3) ^ xr) << 4) + (e & 4) * 2;
                *(uint2*)(AH + sw) = make_uint2(h01, h23);
                *(uint2*)(AL + sw) = make_uint2(l01, l23);
            }
        }
        __syncthreads();   // A tile visible to all warps

        // prefetch next z tile (long-latency, overlaps MMA phase)
        if (t + 1 < NTILES) {
            const float4* zp = (const float4*)(zrow + (size_t)(t + 1) * TM * E_);
            #pragma unroll
            for (int j = 0; j < 8; j++) zreg[j] = zp[j];
        }

        // ---- MMA: 32m x 64n per warp, 3-term split, K=128
        float acc[2][8][4];
        #pragma unroll
        for (int mt = 0; mt < 2; mt++)
            #pragma unroll
            for (int nt = 0; nt < 8; nt++)
                #pragma unroll
                for (int i = 0; i < 4; i++) acc[mt][nt][i] = 0.f;

        #pragma unroll 2
        for (int ks = 0; ks < 8; ks++) {
            uint32_t ah[2][4], al[2][4];
            const uint32_t aoff = arow + ((uint32_t)((ks * 2 + asel) ^ laneX) << 4);
            ldsm_x4(ah[0], aoff + SM_AH);
            ldsm_x4(ah[1], aoff + SM_AH + 16 * 256);
            ldsm_x4(al[0], aoff + SM_AL);
            ldsm_x4(al[1], aoff + SM_AL + 16 * 256);
            const uint32_t boff = ((uint32_t)((ks * 2 + bsel) ^ laneX) << 4);
            #pragma unroll
            for (int ntp = 0; ntp < 4; ntp++) {
                uint32_t bh[4], bl[4];
                const uint32_t ba = brow + (uint32_t)ntp * (16 * 256) + boff;
                ldsm_x4(bh, ba + SM_WH);
                ldsm_x4(bl, ba + SM_WL);
                #pragma unroll
                for (int mt = 0; mt < 2; mt++) {
                    MMA_BF16(acc[mt][2 * ntp],     ah[mt], bh[0], bh[1]);
                    MMA_BF16(acc[mt][2 * ntp + 1], ah[mt], bh[2], bh[3]);
                    MMA_BF16(acc[mt][2 * ntp],     ah[mt], bl[0], bl[1]);
                    MMA_BF16(acc[mt][2 * ntp + 1], ah[mt], bl[2], bl[3]);
                    MMA_BF16(acc[mt][2 * ntp],     al[mt], bh[0], bh[1]);
                    MMA_BF16(acc[mt][2 * ntp + 1], al[mt], bh[2], bh[3]);
                }
            }
        }

        // ---- scores straight from fragments: col pair (2j,2j+1) = (p1[j], p2[j]), j = h*16+d
        #pragma unroll
        for (int hh = 0; hh < 2; hh++) {
            const int h = nq * 2 + hh;
            const float* kh = k + (((size_t)b * H_ + h) * N_) * D_;
            const float* qh = q_sm + h * 16;
            float sa[2][2] = {{0.f, 0.f}, {0.f, 0.f}};
            #pragma unroll
            for (int ntl = 0; ntl < 4; ntl++) {
                const int nt = hh * 4 + ntl;
                const int d = ntl * 4 + tig;
                const float qv = qh[d];
                #pragma unroll
                for (int mt = 0; mt < 2; mt++) {
                    const int mg = t * TM + mblk + mt * 16 + g;
                    float kv0 = kh[(size_t)mg * 16 + d];
                    float kv1 = kh[(size_t)(mg + 8) * 16 + d];
                    sa[mt][0] += (qv + acc[mt][nt][0]) * (kv0 + acc[mt][nt][1]);
                    sa[mt][1] += (qv + acc[mt][nt][2]) * (kv1 + acc[mt][nt][3]);
                }
            }
            #pragma unroll
            for (int mt = 0; mt < 2; mt++)
                #pragma unroll
                for (int r = 0; r < 2; r++) {
                    float s = sa[mt][r];
                    s += __shfl_xor_sync(0xffffffffu, s, 1);
                    s += __shfl_xor_sync(0xffffffffu, s, 2);
                    if (tig == 0) {
                        const int mg = t * TM + mblk + mt * 16 + g + r * 8;
                        s_sm[h * N_ + mg] = s * 0.25f;   // 1/sqrt(D), D=16
                    }
                }
        }
        __syncthreads();   // all warps done with A_sm before next tile overwrites
    }

    // ---- softmax + output: 2 warps per head (wid&7 = head, wid>>3 = m-half)
    {
        const int h    = wid & 7;
        const int half = wid >> 3;
        float* srow = s_sm + h * N_;

        // global max: both warps redundantly scan the full row (read-only)
        float mx = -1e30f;
        for (int m = lane; m < N_; m += 32) mx = fmaxf(mx, srow[m]);
        #pragma unroll
        for (int o = 16; o > 0; o >>= 1) mx = fmaxf(mx, __shfl_xor_sync(0xffffffffu, mx, o));

        // exp own half, partial sum
        float psum = 0.f;
        const int mbeg = half * (N_ / 2);
        for (int m = mbeg + lane; m < mbeg + N_ / 2; m += 32) {
            float e = __expf(srow[m] - mx);
            srow[m] = e;
            psum += e;
        }
        #pragma unroll
        for (int o = 16; o > 0; o >>= 1) psum += __shfl_xor_sync(0xffffffffu, psum, o);
        if (lane == 0) red_sm[h * 2 + half] = psum;
        __syncthreads();
        const float sum = red_sm[h * 2] + red_sm[h * 2 + 1];

        // output partial over own 256-m half; lane = d + 16*sub, sub splits into 2x128
        const int d   = lane & 15;
        const int sub = lane >> 4;
        const float* vp = v + (((size_t)b * H_ + h) * N_) * D_;
        float oacc = 0.f;
        const int m0 = mbeg + sub * (N_ / 4);
        #pragma unroll 4
        for (int m = m0; m < m0 + N_ / 4; m++)
            oacc += srow[m] * vp[(size_t)m * D_ + d];
        oacc += __shfl_xor_sync(0xffffffffu, oacc, 16);
        if (half == 1 && sub == 0) obuf[h * 16 + d] = oacc;
        __syncthreads();
        if (half == 0 && sub == 0)
            out[((size_t)b * N_ + n) * HD + h * 16 + d] = (oacc + obuf[h * 16 + d]) / sum;
    }
}

extern "C" void kernel_launch(void* const* d_in, const int* in_sizes, int n_in,
                              void* d_out, int out_size) {
    const float* q   = (const float*)d_in[0];
    const float* k   = (const float*)d_in[1];
    const float* v   = (const float*)d_in[2];
    const float* z   = (const float*)d_in[3];
    const float* Wz1 = (const float*)d_in[4];
    const float* Wz2 = (const float*)d_in[5];
    float* out = (float*)d_out;

    cudaFuncSetAttribute(mixed_attn_hmma,
                         cudaFuncAttributeMaxDynamicSharedMemorySize, SM_TOTAL);
    dim3 grid(N_, B_);
    mixed_attn_hmma<<<grid, THREADS, SM_TOTAL>>>(q, k, v, z, Wz1, Wz2, out);
}